// round 7
// baseline (speedup 1.0000x reference)
#include <cuda_runtime.h>

typedef unsigned long long u64;

// ---------------- packed f32x2 primitives (sm_103a) ----------------
static __device__ __forceinline__ u64 pk(float lo, float hi) {
    u64 r; asm("mov.b64 %0, {%1, %2};" : "=l"(r) : "f"(lo), "f"(hi)); return r;
}
static __device__ __forceinline__ void upk(u64 v, float& lo, float& hi) {
    asm("mov.b64 {%0, %1}, %2;" : "=f"(lo), "=f"(hi) : "l"(v));
}
static __device__ __forceinline__ u64 ffma2(u64 a, u64 b, u64 c) {
    u64 d; asm("fma.rn.f32x2 %0, %1, %2, %3;" : "=l"(d) : "l"(a), "l"(b), "l"(c)); return d;
}

// single-MUFU tanh (MUFU.TANH)
static __device__ __forceinline__ float tanh_hw(float x) {
    float y; asm("tanh.approx.f32 %0, %1;" : "=f"(y) : "f"(x)); return y;
}

// ---------------- shared-memory weight layout (plain floats, padded cols) ----------------
static constexpr int OW1  = 0;      // [2][32]
static constexpr int OB1  = 64;     // [32]
static constexpr int OW2  = 96;     // [30][32]
static constexpr int OB2  = 1056;   // [32]
static constexpr int OW3  = 1088;   // [30][32]
static constexpr int OB3  = 2048;   // [32]
static constexpr int OW4  = 2080;   // [30][8]
static constexpr int OB4  = 2320;   // [8]
static constexpr int OP1  = 2328;   // [2][16]
static constexpr int OPB1 = 2360;   // [16]
static constexpr int OP2  = 2376;   // [15][16]
static constexpr int OPB2 = 2616;   // [16]
static constexpr int OP3  = 2632;   // [15][16]
static constexpr int OPB3 = 2872;   // [16]
static constexpr int OP4  = 2888;   // [15][4]
static constexpr int OPB4 = 2948;   // [4]
static constexpr int SMW_TOTAL = 2952;  // floats = 11808 B

// ---------------- dense layer with FUSED input tanh ----------------
// If ACT, the input values are pre-activations: tanh is applied per-k inside
// the loop, so MUFU issue interleaves with the FFMA2 stream (no burst phases).
template <int NI, int NOP, bool ACT>
static __device__ __forceinline__ void dense_pp(const float* __restrict__ Wm,
                                                const float* __restrict__ Bs,
                                                const u64* __restrict__ hA,
                                                const u64* __restrict__ hB,
                                                u64* __restrict__ accA,
                                                u64* __restrict__ accB)
{
#pragma unroll
    for (int jp = 0; jp < NOP / 2; jp++) {
        float2 b = *(const float2*)(Bs + 2 * jp);
        u64 bp = pk(b.x, b.y);
        accA[jp] = bp; accB[jp] = bp;
    }
#pragma unroll
    for (int k = 0; k < NI; k++) {
        float alo, ahi; upk(hA[k >> 1], alo, ahi);
        float blo, bhi; upk(hB[k >> 1], blo, bhi);
        float av = (k & 1) ? ahi : alo;
        float bv = (k & 1) ? bhi : blo;
        if (ACT) { av = tanh_hw(av); bv = tanh_hw(bv); }
        u64 dA = pk(av, av);
        u64 dB = pk(bv, bv);
#pragma unroll
        for (int jq = 0; jq < NOP / 4; jq++) {
            float4 w = *(const float4*)(Wm + k * NOP + 4 * jq);
            u64 w01 = pk(w.x, w.y), w23 = pk(w.z, w.w);
            accA[2 * jq]     = ffma2(w01, dA, accA[2 * jq]);
            accA[2 * jq + 1] = ffma2(w23, dA, accA[2 * jq + 1]);
            accB[2 * jq]     = ffma2(w01, dB, accB[2 * jq]);
            accB[2 * jq + 1] = ffma2(w23, dB, accB[2 * jq + 1]);
        }
    }
}

// ---------------- half-angle: sin(θ/2), cos(θ/2) from cosθ, sinθ ----------------
static __device__ __forceinline__ void halfang(float c, float sn, float& sh, float& ch) {
    ch = sqrtf(fmaxf(0.0f, 0.5f * (1.0f + c)));
    float sh_a = copysignf(sqrtf(fmaxf(0.0f, 0.5f * (1.0f - c))), sn);
    float sh_b = __fdividef(0.5f * sn, ch);
    sh = (ch > 0.1f) ? sh_b : sh_a;
}

// ---------------- per-point epilogue ----------------
static __device__ __forceinline__ float epilogue(
    float x0, float x1, float r, float cb, float sb,
    const float* wv, const float* pv, float lm)
{
    float s2  = fmaf(x0, x0, x1 * x1);
    float ri0 = rsqrtf(s2);
    float r0  = s2 * ri0;
    float c   = x0 * ri0, sn = x1 * ri0;
    float sh, ch; halfang(c, sn, sh, ch);
    float sq  = sqrtf(r0);
    float v0  = sq * sh;
    float v1  = r0 * sn;
    float v2  = (r0 * sq) * fmaf(sn, ch, c * sh);
    float shb, chb; halfang(cb, sb, shb, chb);
    float u0 = shb, u1 = sb, u2 = fmaf(sb, chb, cb * shb);
    float t  = fminf(fmaxf(fmaf(2.5f, r, -1.25f), 0.0f), 1.0f);
    float t3 = t * t * t;
    float yita = fmaf(fmaf(fmaf(-6.0f, t, 15.0f), t, -10.0f), t3, 1.0f);
    float rp = wv[0] + yita * wv[4]
             + fmaf(wv[5], yita, wv[1]) * v0
             + fmaf(wv[6], yita, wv[2]) * v1
             + fmaf(wv[7], yita, wv[3]) * v2;
    float s  = fmaf(pv[1], u0, fmaf(pv[2], u1, fmaf(pv[3], u2, pv[0])));
    float sp = s * yita * __powf(r, lm);
    return rp + sp;
}

// ---------------- kernel: 2 points per thread, fused-tanh dense chain ----------------
__global__ void __launch_bounds__(128)
mlp2d_kernel(const float* __restrict__ x,   const float* __restrict__ imv,
             const float* __restrict__ lmbd,
             const float* __restrict__ Ww1, const float* __restrict__ bw1,
             const float* __restrict__ Ww2, const float* __restrict__ bw2,
             const float* __restrict__ Ww3, const float* __restrict__ bw3,
             const float* __restrict__ Ww4, const float* __restrict__ bw4,
             const float* __restrict__ Wp1, const float* __restrict__ bp1,
             const float* __restrict__ Wp2, const float* __restrict__ bp2,
             const float* __restrict__ Wp3, const float* __restrict__ bp3,
             const float* __restrict__ Wp4, const float* __restrict__ bp4,
             float* __restrict__ out, int N)
{
    __shared__ alignas(16) float smw[SMW_TOTAL];
    __shared__ float scons[3];

    const int tid = threadIdx.x;
    {
        struct Seg { int off; int rows; int cols; int pad; };
        const Seg segs[16] = {
            {OW1, 2, 30, 32},  {OB1, 1, 30, 32},
            {OW2, 30, 30, 32}, {OB2, 1, 30, 32},
            {OW3, 30, 30, 32}, {OB3, 1, 30, 32},
            {OW4, 30, 8, 8},   {OB4, 1, 8, 8},
            {OP1, 2, 15, 16},  {OPB1, 1, 15, 16},
            {OP2, 15, 15, 16}, {OPB2, 1, 15, 16},
            {OP3, 15, 15, 16}, {OPB3, 1, 15, 16},
            {OP4, 15, 4, 4},   {OPB4, 1, 4, 4},
        };
        const float* srcs[16] = {Ww1, bw1, Ww2, bw2, Ww3, bw3, Ww4, bw4,
                                 Wp1, bp1, Wp2, bp2, Wp3, bp3, Wp4, bp4};
        for (int a = 0; a < 16; a++) {
            const Seg s = segs[a];
            const float* src = srcs[a];
            int n = s.rows * s.pad;
            for (int t = tid; t < n; t += 128) {
                int r = t / s.pad, c = t - r * s.pad;
                smw[s.off + t] = (c < s.cols) ? src[r * s.cols + c] : 0.0f;
            }
        }
        if (tid == 0) { scons[0] = imv[0]; scons[1] = imv[1]; scons[2] = lmbd[0]; }
    }
    __syncthreads();

    long long pair = (long long)blockIdx.x * 128 + tid;
    int i0 = (int)(2 * pair);
    if (i0 >= N) return;
    const bool full = (i0 + 1 < N);

    float xa0, xa1, xB0, xB1;
    if (full) {
        float4 p = *(const float4*)(x + 2 * (size_t)i0);
        xa0 = p.x; xa1 = p.y; xB0 = p.z; xB1 = p.w;
    } else {
        float2 p = *(const float2*)(x + 2 * (size_t)i0);
        xa0 = xB0 = p.x; xa1 = xB1 = p.y;
    }

    // ---- w-MLP: 2 -> 30 -> 30 -> 30 -> 8, tanh fused into consumer layers ----
    u64 A1[16], B1[16], A2[16], B2[16];
    {
        u64 hA[1] = {pk(xa0, xa1)};
        u64 hB[1] = {pk(xB0, xB1)};
        dense_pp<2, 32, false>(smw + OW1, smw + OB1, hA, hB, A1, B1);
    }
    dense_pp<30, 32, true>(smw + OW2, smw + OB2, A1, B1, A2, B2);
    dense_pp<30, 32, true>(smw + OW3, smw + OB3, A2, B2, A1, B1);
    u64 WoA[4], WoB[4];
    dense_pp<30, 8, true>(smw + OW4, smw + OB4, A1, B1, WoA, WoB);

    // ---- geometry about imv ----
    const float im0 = scons[0], im1 = scons[1], lm = scons[2];

    float dA0 = xa0 - im0, dA1 = xa1 - im1;
    float rsA = fmaf(dA0, dA0, dA1 * dA1);
    float riA = rsqrtf(rsA);
    float rA  = rsA * riA;
    float cbA = dA0 * riA, sbA = dA1 * riA;

    float dB0 = xB0 - im0, dB1 = xB1 - im1;
    float rsB = fmaf(dB0, dB0, dB1 * dB1);
    float riB = rsqrtf(rsB);
    float rB  = rsB * riB;
    float cbB = dB0 * riB, sbB = dB1 * riB;

    // ---- phi-MLP: 2 -> 15 -> 15 -> 15 -> 4 (padded to 16), fused tanh ----
    u64 PA[8], PB[8], QA[8], QB[8];
    {
        u64 hA[1] = {pk(cbA, sbA)};
        u64 hB[1] = {pk(cbB, sbB)};
        dense_pp<2, 16, false>(smw + OP1, smw + OPB1, hA, hB, PA, PB);
    }
    dense_pp<15, 16, true>(smw + OP2, smw + OPB2, PA, PB, QA, QB);
    dense_pp<15, 16, true>(smw + OP3, smw + OPB3, QA, QB, PA, PB);
    u64 PhA[2], PhB[2];
    dense_pp<15, 4, true>(smw + OP4, smw + OPB4, PA, PB, PhA, PhB);

    // ---- unpack heads and finish per point ----
    float wA[8], wB[8], pA_[4], pB_[4];
#pragma unroll
    for (int j = 0; j < 4; j++) { upk(WoA[j], wA[2 * j], wA[2 * j + 1]);
                                  upk(WoB[j], wB[2 * j], wB[2 * j + 1]); }
#pragma unroll
    for (int j = 0; j < 2; j++) { upk(PhA[j], pA_[2 * j], pA_[2 * j + 1]);
                                  upk(PhB[j], pB_[2 * j], pB_[2 * j + 1]); }

    float eA = epilogue(xa0, xa1, rA, cbA, sbA, wA, pA_, lm);
    if (full) {
        float eB = epilogue(xB0, xB1, rB, cbB, sbB, wB, pB_, lm);
        *(float2*)(out + i0) = make_float2(eA, eB);
    } else {
        out[i0] = eA;
    }
}

extern "C" void kernel_launch(void* const* d_in, const int* in_sizes, int n_in,
                              void* d_out, int out_size)
{
    const float* x    = (const float*)d_in[0];
    const float* imv  = (const float*)d_in[1];
    const float* lmbd = (const float*)d_in[2];
    const float* Ww1  = (const float*)d_in[3];
    const float* bw1  = (const float*)d_in[4];
    const float* Ww2  = (const float*)d_in[5];
    const float* bw2  = (const float*)d_in[6];
    const float* Ww3  = (const float*)d_in[7];
    const float* bw3  = (const float*)d_in[8];
    const float* Ww4  = (const float*)d_in[9];
    const float* bw4  = (const float*)d_in[10];
    const float* Wp1  = (const float*)d_in[11];
    const float* bp1  = (const float*)d_in[12];
    const float* Wp2  = (const float*)d_in[13];
    const float* bp2  = (const float*)d_in[14];
    const float* Wp3  = (const float*)d_in[15];
    const float* bp3  = (const float*)d_in[16];
    const float* Wp4  = (const float*)d_in[17];
    const float* bp4  = (const float*)d_in[18];

    int N = out_size;
    long long pairs = ((long long)N + 1) / 2;
    int blocks = (int)((pairs + 127) / 128);

    mlp2d_kernel<<<blocks, 128>>>(x, imv, lmbd,
                                  Ww1, bw1, Ww2, bw2, Ww3, bw3, Ww4, bw4,
                                  Wp1, bp1, Wp2, bp2, Wp3, bp3, Wp4, bp4,
                                  (float*)d_out, N);
}

// round 9
// speedup vs baseline: 1.0027x; 1.0027x over previous
#include <cuda_runtime.h>
#include <cuda_fp16.h>

typedef unsigned long long u64;
typedef unsigned int u32;

// ---------------- packed f32x2 primitives (sm_103a) ----------------
static __device__ __forceinline__ u64 pk(float lo, float hi) {
    u64 r; asm("mov.b64 %0, {%1, %2};" : "=l"(r) : "f"(lo), "f"(hi)); return r;
}
static __device__ __forceinline__ void upk(u64 v, float& lo, float& hi) {
    asm("mov.b64 {%0, %1}, %2;" : "=f"(lo), "=f"(hi) : "l"(v));
}
static __device__ __forceinline__ u64 ffma2(u64 a, u64 b, u64 c) {
    u64 d; asm("fma.rn.f32x2 %0, %1, %2, %3;" : "=l"(d) : "l"(a), "l"(b), "l"(c)); return d;
}

// single-MUFU tanh (MUFU.TANH)
static __device__ __forceinline__ float tanh_hw(float x) {
    float y; asm("tanh.approx.f32 %0, %1;" : "=f"(y) : "f"(x)); return y;
}

// tanh both halves of a packed fp32 pair, compress to fp16x2 (1 reg / 2 acts)
// fp16 (11-bit mantissa): per-act rounding ~2.4e-4 vs bf16's ~2e-3.
static __device__ __forceinline__ u32 pack_tanh_h(u64 z) {
    float a, b; upk(z, a, b);
    float2 f; f.x = tanh_hw(a); f.y = tanh_hw(b);
    __half2 h = __float22half2_rn(f);
    return *reinterpret_cast<u32*>(&h);
}

// ---------------- shared-memory weight layout (plain floats, padded cols) ----------------
static constexpr int OW1  = 0;      // [2][32]
static constexpr int OB1  = 64;     // [32]
static constexpr int OW2  = 96;     // [30][32]
static constexpr int OB2  = 1056;   // [32]
static constexpr int OW3  = 1088;   // [30][32]
static constexpr int OB3  = 2048;   // [32]
static constexpr int OW4  = 2080;   // [30][8]
static constexpr int OB4  = 2320;   // [8]
static constexpr int OP1  = 2328;   // [2][16]
static constexpr int OPB1 = 2360;   // [16]
static constexpr int OP2  = 2376;   // [15][16]
static constexpr int OPB2 = 2616;   // [16]
static constexpr int OP3  = 2632;   // [15][16]
static constexpr int OPB3 = 2872;   // [16]
static constexpr int OP4  = 2888;   // [15][4]
static constexpr int OPB4 = 2948;   // [4]
static constexpr int SMW_TOTAL = 2952;  // floats = 11808 B

// ---------------- dense layer: fp16x2 activations in, fp32-pair accs out ----------------
template <int NI, int NOP>
static __device__ __forceinline__ void dense_h(const float* __restrict__ Wm,
                                               const float* __restrict__ Bs,
                                               const u32* __restrict__ hA,
                                               const u32* __restrict__ hB,
                                               u64* __restrict__ accA,
                                               u64* __restrict__ accB)
{
#pragma unroll
    for (int jp = 0; jp < NOP / 2; jp++) {
        float2 b = *(const float2*)(Bs + 2 * jp);
        u64 bp = pk(b.x, b.y);
        accA[jp] = bp; accB[jp] = bp;
    }
#pragma unroll
    for (int k = 0; k < NI; k++) {
        float2 fa = __half22float2(*reinterpret_cast<const __half2*>(&hA[k >> 1]));
        float2 fb = __half22float2(*reinterpret_cast<const __half2*>(&hB[k >> 1]));
        float av = (k & 1) ? fa.y : fa.x;
        float bv = (k & 1) ? fb.y : fb.x;
        u64 dA = pk(av, av);
        u64 dB = pk(bv, bv);
#pragma unroll
        for (int jq = 0; jq < NOP / 4; jq++) {
            float4 w = *(const float4*)(Wm + k * NOP + 4 * jq);
            u64 w01 = pk(w.x, w.y), w23 = pk(w.z, w.w);
            accA[2 * jq]     = ffma2(w01, dA, accA[2 * jq]);
            accA[2 * jq + 1] = ffma2(w23, dA, accA[2 * jq + 1]);
            accB[2 * jq]     = ffma2(w01, dB, accB[2 * jq]);
            accB[2 * jq + 1] = ffma2(w23, dB, accB[2 * jq + 1]);
        }
    }
}

// fp32 dense (for the phi-MLP; activations stay as packed fp32 pairs)
template <int NI, int NOP>
static __device__ __forceinline__ void dense_pp(const float* __restrict__ Wm,
                                                const float* __restrict__ Bs,
                                                const u64* __restrict__ hA,
                                                const u64* __restrict__ hB,
                                                u64* __restrict__ accA,
                                                u64* __restrict__ accB)
{
#pragma unroll
    for (int jp = 0; jp < NOP / 2; jp++) {
        float2 b = *(const float2*)(Bs + 2 * jp);
        u64 bp = pk(b.x, b.y);
        accA[jp] = bp; accB[jp] = bp;
    }
#pragma unroll
    for (int k = 0; k < NI; k++) {
        float alo, ahi; upk(hA[k >> 1], alo, ahi);
        float blo, bhi; upk(hB[k >> 1], blo, bhi);
        float av = (k & 1) ? ahi : alo;
        float bv = (k & 1) ? bhi : blo;
        u64 dA = pk(av, av);
        u64 dB = pk(bv, bv);
#pragma unroll
        for (int jq = 0; jq < NOP / 4; jq++) {
            float4 w = *(const float4*)(Wm + k * NOP + 4 * jq);
            u64 w01 = pk(w.x, w.y), w23 = pk(w.z, w.w);
            accA[2 * jq]     = ffma2(w01, dA, accA[2 * jq]);
            accA[2 * jq + 1] = ffma2(w23, dA, accA[2 * jq + 1]);
            accB[2 * jq]     = ffma2(w01, dB, accB[2 * jq]);
            accB[2 * jq + 1] = ffma2(w23, dB, accB[2 * jq + 1]);
        }
    }
}

// first layer: two raw fp32 inputs per point
template <int NOP>
static __device__ __forceinline__ void dense_f2(const float* __restrict__ Wm,
                                                const float* __restrict__ Bs,
                                                float a0, float a1, float b0, float b1,
                                                u64* __restrict__ accA,
                                                u64* __restrict__ accB)
{
#pragma unroll
    for (int jp = 0; jp < NOP / 2; jp++) {
        float2 b = *(const float2*)(Bs + 2 * jp);
        u64 bp = pk(b.x, b.y);
        accA[jp] = bp; accB[jp] = bp;
    }
#pragma unroll
    for (int k = 0; k < 2; k++) {
        float av = k ? a1 : a0;
        float bv = k ? b1 : b0;
        u64 dA = pk(av, av);
        u64 dB = pk(bv, bv);
#pragma unroll
        for (int jq = 0; jq < NOP / 4; jq++) {
            float4 w = *(const float4*)(Wm + k * NOP + 4 * jq);
            u64 w01 = pk(w.x, w.y), w23 = pk(w.z, w.w);
            accA[2 * jq]     = ffma2(w01, dA, accA[2 * jq]);
            accA[2 * jq + 1] = ffma2(w23, dA, accA[2 * jq + 1]);
            accB[2 * jq]     = ffma2(w01, dB, accB[2 * jq]);
            accB[2 * jq + 1] = ffma2(w23, dB, accB[2 * jq + 1]);
        }
    }
}

template <int NP>
static __device__ __forceinline__ void act_compress_h(const u64* zA, const u64* zB,
                                                      u32* hA, u32* hB) {
#pragma unroll
    for (int j = 0; j < NP; j++) { hA[j] = pack_tanh_h(zA[j]); hB[j] = pack_tanh_h(zB[j]); }
}

static __device__ __forceinline__ u64 tanh2(u64 v) {
    float a, b; upk(v, a, b);
    return pk(tanh_hw(a), tanh_hw(b));
}
template <int NN>
static __device__ __forceinline__ void tanh_all2(u64* a, u64* b) {
#pragma unroll
    for (int j = 0; j < NN; j++) { a[j] = tanh2(a[j]); b[j] = tanh2(b[j]); }
}

// ---------------- half-angle: sin(θ/2), cos(θ/2) from cosθ, sinθ ----------------
static __device__ __forceinline__ void halfang(float c, float sn, float& sh, float& ch) {
    ch = sqrtf(fmaxf(0.0f, 0.5f * (1.0f + c)));
    float sh_a = copysignf(sqrtf(fmaxf(0.0f, 0.5f * (1.0f - c))), sn);
    float sh_b = __fdividef(0.5f * sn, ch);
    sh = (ch > 0.1f) ? sh_b : sh_a;
}

// ---------------- per-point epilogue ----------------
static __device__ __forceinline__ float epilogue(
    float x0, float x1, float r, float cb, float sb,
    const float* wv, const float* pv, float lm)
{
    float s2  = fmaf(x0, x0, x1 * x1);
    float ri0 = rsqrtf(s2);
    float r0  = s2 * ri0;
    float c   = x0 * ri0, sn = x1 * ri0;
    float sh, ch; halfang(c, sn, sh, ch);
    float sq  = sqrtf(r0);
    float v0  = sq * sh;
    float v1  = r0 * sn;
    float v2  = (r0 * sq) * fmaf(sn, ch, c * sh);
    float shb, chb; halfang(cb, sb, shb, chb);
    float u0 = shb, u1 = sb, u2 = fmaf(sb, chb, cb * shb);
    float t  = fminf(fmaxf(fmaf(2.5f, r, -1.25f), 0.0f), 1.0f);
    float t3 = t * t * t;
    float yita = fmaf(fmaf(fmaf(-6.0f, t, 15.0f), t, -10.0f), t3, 1.0f);
    float rp = wv[0] + yita * wv[4]
             + fmaf(wv[5], yita, wv[1]) * v0
             + fmaf(wv[6], yita, wv[2]) * v1
             + fmaf(wv[7], yita, wv[3]) * v2;
    float s  = fmaf(pv[1], u0, fmaf(pv[2], u1, fmaf(pv[3], u2, pv[0])));
    float sp = s * yita * __powf(r, lm);
    return rp + sp;
}

// ---------------- kernel: 2 points/thread; fp16 acts in w-MLP, fp32 in phi ----------------
__global__ void __launch_bounds__(128, 4)
mlp2d_kernel(const float* __restrict__ x,   const float* __restrict__ imv,
             const float* __restrict__ lmbd,
             const float* __restrict__ Ww1, const float* __restrict__ bw1,
             const float* __restrict__ Ww2, const float* __restrict__ bw2,
             const float* __restrict__ Ww3, const float* __restrict__ bw3,
             const float* __restrict__ Ww4, const float* __restrict__ bw4,
             const float* __restrict__ Wp1, const float* __restrict__ bp1,
             const float* __restrict__ Wp2, const float* __restrict__ bp2,
             const float* __restrict__ Wp3, const float* __restrict__ bp3,
             const float* __restrict__ Wp4, const float* __restrict__ bp4,
             float* __restrict__ out, int N)
{
    __shared__ alignas(16) float smw[SMW_TOTAL];
    __shared__ float scons[3];

    const int tid = threadIdx.x;
    {
        struct Seg { int off; int rows; int cols; int pad; };
        const Seg segs[16] = {
            {OW1, 2, 30, 32},  {OB1, 1, 30, 32},
            {OW2, 30, 30, 32}, {OB2, 1, 30, 32},
            {OW3, 30, 30, 32}, {OB3, 1, 30, 32},
            {OW4, 30, 8, 8},   {OB4, 1, 8, 8},
            {OP1, 2, 15, 16},  {OPB1, 1, 15, 16},
            {OP2, 15, 15, 16}, {OPB2, 1, 15, 16},
            {OP3, 15, 15, 16}, {OPB3, 1, 15, 16},
            {OP4, 15, 4, 4},   {OPB4, 1, 4, 4},
        };
        const float* srcs[16] = {Ww1, bw1, Ww2, bw2, Ww3, bw3, Ww4, bw4,
                                 Wp1, bp1, Wp2, bp2, Wp3, bp3, Wp4, bp4};
        for (int a = 0; a < 16; a++) {
            const Seg s = segs[a];
            const float* src = srcs[a];
            int n = s.rows * s.pad;
            for (int t = tid; t < n; t += 128) {
                int r = t / s.pad, c = t - r * s.pad;
                smw[s.off + t] = (c < s.cols) ? src[r * s.cols + c] : 0.0f;
            }
        }
        if (tid == 0) { scons[0] = imv[0]; scons[1] = imv[1]; scons[2] = lmbd[0]; }
    }
    __syncthreads();

    long long pair = (long long)blockIdx.x * 128 + tid;
    int i0 = (int)(2 * pair);
    if (i0 >= N) return;
    const bool full = (i0 + 1 < N);

    float xa0, xa1, xB0, xB1;
    if (full) {
        float4 p = *(const float4*)(x + 2 * (size_t)i0);
        xa0 = p.x; xa1 = p.y; xB0 = p.z; xB1 = p.w;
    } else {
        float2 p = *(const float2*)(x + 2 * (size_t)i0);
        xa0 = xB0 = p.x; xa1 = xB1 = p.y;
    }

    // ---- w-MLP: 2 -> 30 -> 30 -> 30 -> 8, fp16-compressed activations ----
    u64 ZA[16], ZB[16];          // fp32 pre-activation pairs (accumulators)
    u32 HA[16], HB[16];          // fp16x2 activations

    dense_f2<32>(smw + OW1, smw + OB1, xa0, xa1, xB0, xB1, ZA, ZB);
    act_compress_h<16>(ZA, ZB, HA, HB);
    dense_h<30, 32>(smw + OW2, smw + OB2, HA, HB, ZA, ZB);
    act_compress_h<16>(ZA, ZB, HA, HB);
    dense_h<30, 32>(smw + OW3, smw + OB3, HA, HB, ZA, ZB);
    act_compress_h<16>(ZA, ZB, HA, HB);
    u64 WoA[4], WoB[4];
    dense_h<30, 8>(smw + OW4, smw + OB4, HA, HB, WoA, WoB);

    // ---- geometry about imv ----
    const float im0 = scons[0], im1 = scons[1], lm = scons[2];

    float dA0 = xa0 - im0, dA1 = xa1 - im1;
    float rsA = fmaf(dA0, dA0, dA1 * dA1);
    float riA = rsqrtf(rsA);
    float rA  = rsA * riA;
    float cbA = dA0 * riA, sbA = dA1 * riA;

    float dB0 = xB0 - im0, dB1 = xB1 - im1;
    float rsB = fmaf(dB0, dB0, dB1 * dB1);
    float riB = rsqrtf(rsB);
    float rB  = rsB * riB;
    float cbB = dB0 * riB, sbB = dB1 * riB;

    // ---- phi-MLP: 2 -> 15 -> 15 -> 15 -> 4, full fp32 (reuses w-MLP regs) ----
    u64 PA[8], PB[8], QA[8], QB[8];
    dense_f2<16>(smw + OP1, smw + OPB1, cbA, sbA, cbB, sbB, PA, PB);
    tanh_all2<8>(PA, PB);
    dense_pp<15, 16>(smw + OP2, smw + OPB2, PA, PB, QA, QB);
    tanh_all2<8>(QA, QB);
    dense_pp<15, 16>(smw + OP3, smw + OPB3, QA, QB, PA, PB);
    tanh_all2<8>(PA, PB);
    u64 PhA[2], PhB[2];
    dense_pp<15, 4>(smw + OP4, smw + OPB4, PA, PB, PhA, PhB);

    // ---- unpack heads and finish per point ----
    float wA[8], wB[8], pA_[4], pB_[4];
#pragma unroll
    for (int j = 0; j < 4; j++) { upk(WoA[j], wA[2 * j], wA[2 * j + 1]);
                                  upk(WoB[j], wB[2 * j], wB[2 * j + 1]); }
#pragma unroll
    for (int j = 0; j < 2; j++) { upk(PhA[j], pA_[2 * j], pA_[2 * j + 1]);
                                  upk(PhB[j], pB_[2 * j], pB_[2 * j + 1]); }

    float eA = epilogue(xa0, xa1, rA, cbA, sbA, wA, pA_, lm);
    if (full) {
        float eB = epilogue(xB0, xB1, rB, cbB, sbB, wB, pB_, lm);
        *(float2*)(out + i0) = make_float2(eA, eB);
    } else {
        out[i0] = eA;
    }
}

extern "C" void kernel_launch(void* const* d_in, const int* in_sizes, int n_in,
                              void* d_out, int out_size)
{
    const float* x    = (const float*)d_in[0];
    const float* imv  = (const float*)d_in[1];
    const float* lmbd = (const float*)d_in[2];
    const float* Ww1  = (const float*)d_in[3];
    const float* bw1  = (const float*)d_in[4];
    const float* Ww2  = (const float*)d_in[5];
    const float* bw2  = (const float*)d_in[6];
    const float* Ww3  = (const float*)d_in[7];
    const float* bw3  = (const float*)d_in[8];
    const float* Ww4  = (const float*)d_in[9];
    const float* bw4  = (const float*)d_in[10];
    const float* Wp1  = (const float*)d_in[11];
    const float* bp1  = (const float*)d_in[12];
    const float* Wp2  = (const float*)d_in[13];
    const float* bp2  = (const float*)d_in[14];
    const float* Wp3  = (const float*)d_in[15];
    const float* bp3  = (const float*)d_in[16];
    const float* Wp4  = (const float*)d_in[17];
    const float* bp4  = (const float*)d_in[18];

    int N = out_size;
    long long pairs = ((long long)N + 1) / 2;
    int blocks = (int)((pairs + 127) / 128);

    mlp2d_kernel<<<blocks, 128>>>(x, imv, lmbd,
                                  Ww1, bw1, Ww2, bw2, Ww3, bw3, Ww4, bw4,
                                  Wp1, bp1, Wp2, bp2, Wp3, bp3, Wp4, bp4,
                                  (float*)d_out, N);
}